// round 5
// baseline (speedup 1.0000x reference)
#include <cuda_runtime.h>
#include <math_constants.h>

#define BS 8
#define NQ 1000
#define D 256
#define NROWS (BS * NQ)
#define TOPK 10
#define MAX_PAIRS (NROWS * TOPK)
#define RPB 4      // rows per group in GEMV kernels
#define MROWS 10   // rows per block in mask kernel
#define GT 256     // threads in GEMV kernels: 128 colpairs x 2 k-halves
#define NCOL2 128  // D/2 column pairs
#define GRID_GEMV 444

typedef unsigned long long u64;

// ---------------- scratch (no allocations allowed) ----------------
__device__ float g_P[NROWS * D];      // P = id_token @ W3 (active rows only)
__device__ float g_cur[NROWS * D];    // running max of masked features (active rows only)
__device__ int   g_pairs[MAX_PAIRS * 2];
__device__ int   g_pair_count;
__device__ int   g_flag[NROWS];
__device__ int   g_idrows[NROWS];
__device__ int   g_nid;
__device__ int   g_outrows[NROWS];
__device__ int   g_nout;

__global__ void k_reset() {
    const int i = blockIdx.x * 256 + threadIdx.x;
    if (i < NROWS) g_flag[i] = 0;
    if (i == 0) { g_pair_count = 0; g_nid = 0; g_nout = 0; }
}

__device__ __forceinline__ void atomicMaxFloat(float* addr, float v) {
    if (v >= 0.0f) atomicMax((int*)addr, __float_as_int(v));
    else           atomicMin((unsigned int*)addr, __float_as_uint(v));
}

// ---------------- f32x2 packed helpers ----------------
__device__ __forceinline__ u64 fma2(u64 a, u64 b, u64 c) {
    u64 d; asm("fma.rn.f32x2 %0, %1, %2, %3;" : "=l"(d) : "l"(a), "l"(b), "l"(c)); return d;
}
__device__ __forceinline__ u64 add2(u64 a, u64 b) {
    u64 d; asm("add.rn.f32x2 %0, %1, %2;" : "=l"(d) : "l"(a), "l"(b)); return d;
}
__device__ __forceinline__ u64 pack2(float lo, float hi) {
    u64 d; asm("mov.b64 %0, {%1, %2};" : "=l"(d) : "f"(lo), "f"(hi)); return d;
}
__device__ __forceinline__ void unpack2(u64 v, float& lo, float& hi) {
    asm("mov.b64 {%0, %1}, %2;" : "=f"(lo), "=f"(hi) : "l"(v));
}

// Half-K packed GEMV: acc[r] (f32x2 over cols 2*col2, 2*col2+1) +=
//   sum_{k in [k_lo, k_lo+128)} Xd[r][k](dup) * W[k][2*col2 .. 2*col2+1]
// Weight stream prefetched one 8-k tile ahead.
__device__ __forceinline__ void gemv2(const u64 (*Xd)[D], const float* __restrict__ W,
                                      int col2, int k_lo, u64 acc[RPB]) {
#pragma unroll
    for (int r = 0; r < RPB; r++) acc[r] = 0ull;
    const float* Wc = W + 2 * col2;
    u64 wA[8], wB[8];
#pragma unroll
    for (int i = 0; i < 8; i++) wA[i] = *(const u64*)(Wc + (k_lo + i) * D);
#pragma unroll
    for (int i = 0; i < 8; i++) wB[i] = *(const u64*)(Wc + (k_lo + 8 + i) * D);
    for (int k0 = k_lo; k0 < k_lo + 128; k0 += 8) {
        u64 w[8];
#pragma unroll
        for (int i = 0; i < 8; i++) w[i] = wA[i];
#pragma unroll
        for (int i = 0; i < 8; i++) wA[i] = wB[i];
        if (k0 + 16 < k_lo + 128) {
#pragma unroll
            for (int i = 0; i < 8; i++) wB[i] = *(const u64*)(Wc + (k0 + 16 + i) * D);
        }
#pragma unroll
        for (int i = 0; i < 8; i += 2) {
#pragma unroll
            for (int r = 0; r < RPB; r++) {
                const ulonglong2 x = *(const ulonglong2*)&Xd[r][k0 + i];
                acc[r] = fma2(x.x, w[i],     acc[r]);
                acc[r] = fma2(x.y, w[i + 1], acc[r]);
            }
        }
    }
}

// ---------------- K2: IoU mask + selection + cur-init + base output ----------------
__global__ __launch_bounds__(256) void k_mask_sel(
    const float* __restrict__ pred, const float* __restrict__ seed,
    const float* __restrict__ tgt,  const float* __restrict__ b5,
    float* __restrict__ out, float* __restrict__ out_mask)
{
    const int base = blockIdx.x * MROWS;
    const int b = base / NQ;
    const int t = threadIdx.x;

    __shared__ float4 s_box[NQ];
    __shared__ float  s_seed[NQ];
    __shared__ int    s_cnt, s_m;
    __shared__ float  sval[256];
    __shared__ int    sidx[256];

    const float rb5 = fmaxf(b5[t], 0.0f);

    for (int j = t; j < NQ; j += 256) {
        s_box[j]  = ((const float4*)pred)[b * NQ + j];
        s_seed[j] = seed[b * NQ + j];
    }
    __syncthreads();

    for (int r = 0; r < MROWS; r++) {
        const int row = base + r;
        const int li  = row - b * NQ;
        if (t == 0) s_cnt = 0;
        __syncthreads();

        const float4 pb = s_box[li];
        const float bx1 = __fsub_rn(pb.x, __fmul_rn(0.5f, pb.z));
        const float by1 = __fsub_rn(pb.y, __fmul_rn(0.5f, pb.w));
        const float bx2 = __fadd_rn(pb.x, __fmul_rn(0.5f, pb.z));
        const float by2 = __fadd_rn(pb.y, __fmul_rn(0.5f, pb.w));
        const float ai  = __fmul_rn(__fsub_rn(bx2, bx1), __fsub_rn(by2, by1));
        const bool negi = (s_seed[li] == 0.0f);

        for (int j = t; j < NQ; j += 256) {
            const float4 q = s_box[j];
            const float qx1 = __fsub_rn(q.x, __fmul_rn(0.5f, q.z));
            const float qy1 = __fsub_rn(q.y, __fmul_rn(0.5f, q.w));
            const float qx2 = __fadd_rn(q.x, __fmul_rn(0.5f, q.z));
            const float qy2 = __fadd_rn(q.y, __fmul_rn(0.5f, q.w));
            const float aj  = __fmul_rn(__fsub_rn(qx2, qx1), __fsub_rn(qy2, qy1));
            const float w = fmaxf(__fsub_rn(fminf(bx2, qx2), fmaxf(bx1, qx1)), 0.0f);
            const float h = fmaxf(__fsub_rn(fminf(by2, qy2), fmaxf(by1, qy1)), 0.0f);
            const float inter = __fmul_rn(w, h);
            const float uni = __fsub_rn(__fadd_rn(ai, aj), inter);
            const float iou = __fdiv_rn(inter, uni);
            const bool attn = (iou >= 0.5f);
            out_mask[(size_t)row * NQ + j] = attn ? 1.0f : 0.0f;
            if (attn && negi && (s_seed[j] != 0.0f)) {
                int p = atomicAdd(&s_cnt, 1);
                if (p < 256) { sval[p] = iou; sidx[p] = j; }
            }
        }
        __syncthreads();

        if (t == 0) {
            int cnt = min(s_cnt, 256);
            int m;
            int sel[TOPK];
            if (cnt <= TOPK) {
                m = cnt;
                for (int q = 0; q < cnt; q++) sel[q] = sidx[q];
            } else {
                m = TOPK;
                for (int rr = 0; rr < TOPK; rr++) {
                    float best = -1.0f; int bj = 0x7fffffff; int bp = -1;
                    for (int p = 0; p < cnt; p++) {
                        float v = sval[p]; int j = sidx[p];
                        if (v > best || (v == best && j < bj)) { best = v; bj = j; bp = p; }
                    }
                    sel[rr] = bj;
                    sval[bp] = -1.0f;
                }
            }
            s_m = m;
            if (m > 0) {
                int pbase = atomicAdd(&g_pair_count, m);
                for (int q = 0; q < m; q++) {
                    g_pairs[2 * (pbase + q)]     = row;
                    g_pairs[2 * (pbase + q) + 1] = sel[q];
                    g_flag[b * NQ + sel[q]] = 1;
                }
                g_flag[row] = 1;
                int op = atomicAdd(&g_nout, 1);
                g_outrows[op] = row;
            }
        }
        __syncthreads();
        const int m = s_m;
        if (m == 0) {
            const float neg = 1.0f - s_seed[li];
            out[(size_t)row * D + t] = tgt[(size_t)row * D + t] + rb5 * neg;
        } else {
            g_cur[(size_t)row * D + t] = (m < TOPK) ? 0.0f : -CUDART_INF_F;
        }
    }
}

// ---------------- compaction of id-rows ----------------
__global__ void k_compact() {
    const int i = blockIdx.x * 256 + threadIdx.x;
    if (i < NROWS && g_flag[i]) {
        int p = atomicAdd(&g_nid, 1);
        g_idrows[p] = i;
    }
}

// ---------------- K3: P = (LN(relu(tgt@W1+b1)@W2+b2)*g2+be2) @ W3, active rows ----------------
__global__ __launch_bounds__(GT) void k_idtoken(
    const float* __restrict__ tgt,
    const float* __restrict__ W1, const float* __restrict__ b1,
    const float* __restrict__ W2, const float* __restrict__ b2,
    const float* __restrict__ g2, const float* __restrict__ be2,
    const float* __restrict__ W3)
{
    const int nact = g_nid;
    const int t = threadIdx.x;
    const int col2 = t & (NCOL2 - 1);
    const int half = t >> 7;
    const int k_lo = half << 7;
    const int c0 = 2 * col2;

    __shared__ __align__(16) u64 Tsd[RPB][D];
    __shared__ __align__(16) u64 Hsd[RPB][D];
    __shared__ __align__(16) u64 Ppd[RPB][NCOL2];
    __shared__ float s_mean[RPB], s_rstd[RPB];
    __shared__ int   srow[RPB];

    const float2 bias1 = *(const float2*)(b1 + c0);
    const float2 bias2 = *(const float2*)(b2 + c0);
    const float2 gv    = *(const float2*)(g2 + c0);
    const float2 bev   = *(const float2*)(be2 + c0);

    for (int g0 = blockIdx.x * RPB; g0 < nact; g0 += gridDim.x * RPB) {
        const int ng = min(RPB, nact - g0);
        if (t < RPB) srow[t] = g_idrows[g0 + ((t < ng) ? t : 0)];
        __syncthreads();

        for (int e = t; e < RPB * (D / 4); e += GT) {
            const int p = e >> 6, c = (e & 63) * 4;
            const float4 v = ((const float4*)(tgt + (size_t)srow[p] * D))[e & 63];
            ulonglong2* dst = (ulonglong2*)&Tsd[p][c];
            dst[0] = make_ulonglong2(pack2(v.x, v.x), pack2(v.y, v.y));
            dst[1] = make_ulonglong2(pack2(v.z, v.z), pack2(v.w, v.w));
        }
        __syncthreads();

        u64 acc[RPB];
        // layer 1
        gemv2(Tsd, W1, col2, k_lo, acc);
        if (half == 1) {
#pragma unroll
            for (int r = 0; r < RPB; r++) Ppd[r][col2] = acc[r];
        }
        __syncthreads();
        if (half == 0) {
#pragma unroll
            for (int r = 0; r < RPB; r++) {
                float v0, v1; unpack2(add2(acc[r], Ppd[r][col2]), v0, v1);
                v0 = fmaxf(v0 + bias1.x, 0.0f);
                v1 = fmaxf(v1 + bias1.y, 0.0f);
                *(ulonglong2*)&Hsd[r][c0] = make_ulonglong2(pack2(v0, v0), pack2(v1, v1));
            }
        }
        __syncthreads();

        // layer 2
        gemv2(Hsd, W2, col2, k_lo, acc);
        if (half == 1) {
#pragma unroll
            for (int r = 0; r < RPB; r++) Ppd[r][col2] = acc[r];
        }
        __syncthreads();
        float z0[RPB], z1[RPB];
        if (half == 0) {
#pragma unroll
            for (int r = 0; r < RPB; r++) {
                unpack2(add2(acc[r], Ppd[r][col2]), z0[r], z1[r]);
                z0[r] += bias2.x;
                z1[r] += bias2.y;
                *(ulonglong2*)&Tsd[r][c0] = make_ulonglong2(pack2(z0[r], z0[r]), pack2(z1[r], z1[r]));
            }
        }
        __syncthreads();

        // LayerNorm stats: warp w (w<RPB) handles row w
        if (t < 32 * RPB) {
            const int wid = t >> 5, lid = t & 31;
            float s = 0.0f, sq = 0.0f;
            for (int c = lid; c < D; c += 32) {
                float lo, hi; unpack2(Tsd[wid][c], lo, hi);
                s += lo; sq += lo * lo;
            }
#pragma unroll
            for (int off = 16; off > 0; off >>= 1) {
                s  += __shfl_down_sync(0xffffffff, s,  off);
                sq += __shfl_down_sync(0xffffffff, sq, off);
            }
            if (lid == 0) {
                float m = s * (1.0f / D);
                s_mean[wid] = m;
                s_rstd[wid] = rsqrtf(sq * (1.0f / D) - m * m + 1e-5f);
            }
        }
        __syncthreads();
        if (half == 0) {
#pragma unroll
            for (int r = 0; r < RPB; r++) {
                const float i0 = (z0[r] - s_mean[r]) * s_rstd[r] * gv.x + bev.x;
                const float i1 = (z1[r] - s_mean[r]) * s_rstd[r] * gv.y + bev.y;
                *(ulonglong2*)&Hsd[r][c0] = make_ulonglong2(pack2(i0, i0), pack2(i1, i1));
            }
        }
        __syncthreads();

        // layer 3: P = id @ W3 (b3 applied at pair stage)
        gemv2(Hsd, W3, col2, k_lo, acc);
        if (half == 1) {
#pragma unroll
            for (int r = 0; r < RPB; r++) Ppd[r][col2] = acc[r];
        }
        __syncthreads();
        if (half == 0) {
            for (int r = 0; r < ng; r++) {
                float v0, v1; unpack2(add2(acc[r], Ppd[r][col2]), v0, v1);
                *(float2*)(g_P + (size_t)srow[r] * D + c0) = make_float2(v0, v1);
            }
        }
        __syncthreads();
    }
}

// ---------------- K4a: per-pair: relu(P_i - P_j + b3) @ W4 + b4 -> atomic max ----------------
__global__ __launch_bounds__(GT) void k_feat(
    const float* __restrict__ b3,
    const float* __restrict__ W4, const float* __restrict__ b4)
{
    const int npairs = g_pair_count;
    const int t = threadIdx.x;
    const int col2 = t & (NCOL2 - 1);
    const int half = t >> 7;
    const int k_lo = half << 7;
    const int c0 = 2 * col2;

    __shared__ __align__(16) u64 Dsd[RPB][D];
    __shared__ __align__(16) u64 Ppd[RPB][NCOL2];
    __shared__ int srow[RPB], sj[RPB];

    const float2 bias4 = *(const float2*)(b4 + c0);

    for (int g0 = blockIdx.x * RPB; g0 < npairs; g0 += gridDim.x * RPB) {
        const int ng = min(RPB, npairs - g0);
        if (t < RPB) {
            if (t < ng) {
                srow[t] = g_pairs[2 * (g0 + t)];
                sj[t]   = g_pairs[2 * (g0 + t) + 1];
            } else {
                srow[t] = -1;
            }
        }
        __syncthreads();

        for (int e = t; e < RPB * (D / 4); e += GT) {
            const int p = e >> 6, c = (e & 63) * 4;
            const int row = srow[p];
            ulonglong2* dst = (ulonglong2*)&Dsd[p][c];
            if (row >= 0) {
                const int bbid = row / NQ;
                const float4 a  = ((const float4*)(g_P + (size_t)row * D))[e & 63];
                const float4 nb = ((const float4*)(g_P + (size_t)(bbid * NQ + sj[p]) * D))[e & 63];
                const float4 bv = ((const float4*)b3)[e & 63];
                const float d0 = fmaxf(a.x - nb.x + bv.x, 0.0f);
                const float d1 = fmaxf(a.y - nb.y + bv.y, 0.0f);
                const float d2 = fmaxf(a.z - nb.z + bv.z, 0.0f);
                const float d3 = fmaxf(a.w - nb.w + bv.w, 0.0f);
                dst[0] = make_ulonglong2(pack2(d0, d0), pack2(d1, d1));
                dst[1] = make_ulonglong2(pack2(d2, d2), pack2(d3, d3));
            } else {
                dst[0] = make_ulonglong2(0ull, 0ull);
                dst[1] = make_ulonglong2(0ull, 0ull);
            }
        }
        __syncthreads();

        u64 acc[RPB];
        gemv2(Dsd, W4, col2, k_lo, acc);
        if (half == 1) {
#pragma unroll
            for (int r = 0; r < RPB; r++) Ppd[r][col2] = acc[r];
        }
        __syncthreads();
        if (half == 0) {
            for (int r = 0; r < ng; r++) {
                float v0, v1; unpack2(add2(acc[r], Ppd[r][col2]), v0, v1);
                atomicMaxFloat(&g_cur[(size_t)srow[r] * D + c0],     v0 + bias4.x);
                atomicMaxFloat(&g_cur[(size_t)srow[r] * D + c0 + 1], v1 + bias4.y);
            }
        }
        __syncthreads();
    }
}

// ---------------- K4b: active rows (m>0, neg==1): out = tgt + relu(cur@W5+b5) ----------------
__global__ __launch_bounds__(GT) void k_out_gemv(
    const float* __restrict__ tgt,
    const float* __restrict__ W5, const float* __restrict__ b5,
    float* __restrict__ out)
{
    const int nact = g_nout;
    const int t = threadIdx.x;
    const int col2 = t & (NCOL2 - 1);
    const int half = t >> 7;
    const int k_lo = half << 7;
    const int c0 = 2 * col2;

    __shared__ __align__(16) u64 Csd[RPB][D];
    __shared__ __align__(16) u64 Ppd[RPB][NCOL2];
    __shared__ int srow[RPB];

    const float2 bias5 = *(const float2*)(b5 + c0);

    for (int g0 = blockIdx.x * RPB; g0 < nact; g0 += gridDim.x * RPB) {
        const int ng = min(RPB, nact - g0);
        if (t < RPB) srow[t] = g_outrows[g0 + ((t < ng) ? t : 0)];
        __syncthreads();

        for (int e = t; e < RPB * (D / 4); e += GT) {
            const int p = e >> 6, c = (e & 63) * 4;
            const float4 v = ((const float4*)(g_cur + (size_t)srow[p] * D))[e & 63];
            ulonglong2* dst = (ulonglong2*)&Csd[p][c];
            dst[0] = make_ulonglong2(pack2(v.x, v.x), pack2(v.y, v.y));
            dst[1] = make_ulonglong2(pack2(v.z, v.z), pack2(v.w, v.w));
        }
        __syncthreads();

        u64 acc[RPB];
        gemv2(Csd, W5, col2, k_lo, acc);
        if (half == 1) {
#pragma unroll
            for (int r = 0; r < RPB; r++) Ppd[r][col2] = acc[r];
        }
        __syncthreads();
        if (half == 0) {
            for (int r = 0; r < ng; r++) {
                const int row = srow[r];
                float v0, v1; unpack2(add2(acc[r], Ppd[r][col2]), v0, v1);
                const float2 tg = *(const float2*)(tgt + (size_t)row * D + c0);
                float2 o;
                o.x = tg.x + fmaxf(v0 + bias5.x, 0.0f);
                o.y = tg.y + fmaxf(v1 + bias5.y, 0.0f);
                *(float2*)(out + (size_t)row * D + c0) = o;
            }
        }
        __syncthreads();
    }
}

// ---------------- launch ----------------
extern "C" void kernel_launch(void* const* d_in, const int* in_sizes, int n_in,
                              void* d_out, int out_size) {
    const float* tgt  = (const float*)d_in[0];
    const float* seed = (const float*)d_in[1];
    const float* pred = (const float*)d_in[2];
    const float* W1 = (const float*)d_in[3];  const float* b1 = (const float*)d_in[4];
    const float* W2 = (const float*)d_in[5];  const float* b2 = (const float*)d_in[6];
    const float* g2 = (const float*)d_in[7];  const float* be2 = (const float*)d_in[8];
    const float* W3 = (const float*)d_in[9];  const float* b3 = (const float*)d_in[10];
    const float* W4 = (const float*)d_in[11]; const float* b4 = (const float*)d_in[12];
    const float* W5 = (const float*)d_in[13]; const float* b5 = (const float*)d_in[14];

    float* out = (float*)d_out;                 // cur_tgt: 8*1000*256 floats
    float* out_mask = out + (size_t)NROWS * D;  // attn_mask: 8*1000*1000 floats (0/1)

    k_reset<<<(NROWS + 255) / 256, 256>>>();
    k_mask_sel<<<NROWS / MROWS, 256>>>(pred, seed, tgt, b5, out, out_mask);
    k_compact<<<(NROWS + 255) / 256, 256>>>();
    k_idtoken<<<GRID_GEMV, GT>>>(tgt, W1, b1, W2, b2, g2, be2, W3);
    k_feat<<<GRID_GEMV, GT>>>(b3, W4, b4);
    k_out_gemv<<<GRID_GEMV, GT>>>(tgt, W5, b5, out);
}

// round 6
// speedup vs baseline: 1.1815x; 1.1815x over previous
#include <cuda_runtime.h>
#include <math_constants.h>
#include <cstdint>

#define BS 8
#define NQ 1000
#define D 256
#define NROWS (BS * NQ)
#define TOPK 10
#define MAX_PAIRS (NROWS * TOPK)
#define MROWS 10      // rows per block in mask kernel
#define GROUP 32      // rows/pairs per group in MMA kernels
#define XSTR 520      // words per row of (hi,lo)-pair shared storage (2*256 + 8 pad)
#define KC 16         // k-chunk for W staging
#define GRID_MMA 296
#define SMEM_MMA ((GROUP + KC) * XSTR * 4)   // 99,840 bytes

// ---------------- scratch (no allocations allowed) ----------------
__device__ float g_P[NROWS * D];      // P = id_token @ W3 (active rows only)
__device__ float g_cur[NROWS * D];    // running max of masked features (active rows only)
__device__ int   g_pairs[MAX_PAIRS * 2];
__device__ int   g_pair_count;
__device__ int   g_flag[NROWS];
__device__ int   g_idrows[NROWS];
__device__ int   g_nid;
__device__ int   g_outrows[NROWS];
__device__ int   g_nout;

__global__ void k_reset() {
    const int i = blockIdx.x * 256 + threadIdx.x;
    if (i < NROWS) g_flag[i] = 0;
    if (i == 0) { g_pair_count = 0; g_nid = 0; g_nout = 0; }
}

__device__ __forceinline__ void atomicMaxFloat(float* addr, float v) {
    if (v >= 0.0f) atomicMax((int*)addr, __float_as_int(v));
    else           atomicMin((unsigned int*)addr, __float_as_uint(v));
}

// ---------------- tf32 split helpers (3xTF32 scheme) ----------------
__device__ __forceinline__ void split_tf32(float x, float& hi, float& lo) {
    asm("cvt.rna.tf32.f32 %0, %1;" : "=f"(hi) : "f"(x));
    lo = x - hi;   // exact (hi within one tf32 ulp of x)
}
__device__ __forceinline__ void split4_store(float* dst, float4 v) {
    float h0,l0,h1,l1,h2,l2,h3,l3;
    split_tf32(v.x,h0,l0); split_tf32(v.y,h1,l1);
    split_tf32(v.z,h2,l2); split_tf32(v.w,h3,l3);
    *(float4*)(dst)     = make_float4(h0,l0,h1,l1);
    *(float4*)(dst + 4) = make_float4(h2,l2,h3,l3);
}
__device__ __forceinline__ void split2_store(float* dst, float a, float b) {
    float h0,l0,h1,l1;
    split_tf32(a,h0,l0); split_tf32(b,h1,l1);
    *(float4*)(dst) = make_float4(h0,l0,h1,l1);
}

__device__ __forceinline__ void mma_tf32(float c[4],
    uint32_t a0, uint32_t a1, uint32_t a2, uint32_t a3,
    uint32_t b0, uint32_t b1)
{
    asm volatile(
        "mma.sync.aligned.m16n8k8.row.col.f32.tf32.tf32.f32 "
        "{%0,%1,%2,%3}, {%4,%5,%6,%7}, {%8,%9}, {%0,%1,%2,%3};"
        : "+f"(c[0]), "+f"(c[1]), "+f"(c[2]), "+f"(c[3])
        : "r"(a0), "r"(a1), "r"(a2), "r"(a3), "r"(b0), "r"(b1));
}

// Core: C[8][4] += Xs(32xD, split pairs) @ Wg(DxD), 3xTF32.
// Warp (h,q): rows h*16..+15, cols q*64..+63 (8 n-tiles of 8).
__device__ __forceinline__ void mma_layer(
    const float* Xs, float* Ws, const float* __restrict__ Wg,
    float C[8][4], int h, int q, int g, int tig, int t)
{
#pragma unroll
    for (int nt = 0; nt < 8; nt++)
#pragma unroll
        for (int i = 0; i < 4; i++) C[nt][i] = 0.0f;

    for (int kc = 0; kc < D; kc += KC) {
        __syncthreads();   // Ws free (and first iter: Xs writes visible)
        // cooperative load of W[kc..kc+KC)[0..D) into Ws as (hi,lo) pairs
#pragma unroll
        for (int i = 0; i < 4; i++) {
            const int k  = (t >> 6) + (i << 2);      // 0..15
            const int n4 = (t & 63) << 2;
            const float4 w = *(const float4*)(Wg + (size_t)(kc + k) * D + n4);
            split4_store(Ws + k * XSTR + (n4 << 1), w);
        }
        __syncthreads();
#pragma unroll
        for (int ks = 0; ks < KC; ks += 8) {
            const float* ax = Xs + (size_t)(h * 16 + g) * XSTR + ((kc + ks + tig) << 1);
            const float2 a0 = *(const float2*)(ax);
            const float2 a1 = *(const float2*)(ax + 8 * XSTR);
            const float2 a2 = *(const float2*)(ax + 8);
            const float2 a3 = *(const float2*)(ax + 8 * XSTR + 8);
            const uint32_t a0h=__float_as_uint(a0.x), a0l=__float_as_uint(a0.y);
            const uint32_t a1h=__float_as_uint(a1.x), a1l=__float_as_uint(a1.y);
            const uint32_t a2h=__float_as_uint(a2.x), a2l=__float_as_uint(a2.y);
            const uint32_t a3h=__float_as_uint(a3.x), a3l=__float_as_uint(a3.y);
#pragma unroll
            for (int nt = 0; nt < 8; nt++) {
                const float* bx = Ws + (size_t)(ks + tig) * XSTR + ((q * 64 + nt * 8 + g) << 1);
                const float2 b0 = *(const float2*)(bx);
                const float2 b1 = *(const float2*)(bx + 4 * XSTR);
                const uint32_t b0h=__float_as_uint(b0.x), b0l=__float_as_uint(b0.y);
                const uint32_t b1h=__float_as_uint(b1.x), b1l=__float_as_uint(b1.y);
                mma_tf32(C[nt], a0h,a1h,a2h,a3h, b0h, b1h);
                mma_tf32(C[nt], a0h,a1h,a2h,a3h, b0l, b1l);
                mma_tf32(C[nt], a0l,a1l,a2l,a3l, b0h, b1h);
            }
        }
    }
}

// ---------------- K2: IoU mask + selection + cur-init + base output ----------------
__global__ __launch_bounds__(256) void k_mask_sel(
    const float* __restrict__ pred, const float* __restrict__ seed,
    const float* __restrict__ tgt,  const float* __restrict__ b5,
    float* __restrict__ out, float* __restrict__ out_mask)
{
    const int base = blockIdx.x * MROWS;
    const int b = base / NQ;
    const int t = threadIdx.x;

    __shared__ float4 s_box[NQ];
    __shared__ float  s_seed[NQ];
    __shared__ int    s_cnt, s_m;
    __shared__ float  sval[256];
    __shared__ int    sidx[256];

    const float rb5 = fmaxf(b5[t], 0.0f);

    for (int j = t; j < NQ; j += 256) {
        s_box[j]  = ((const float4*)pred)[b * NQ + j];
        s_seed[j] = seed[b * NQ + j];
    }
    __syncthreads();

    for (int r = 0; r < MROWS; r++) {
        const int row = base + r;
        const int li  = row - b * NQ;
        if (t == 0) s_cnt = 0;
        __syncthreads();

        const float4 pb = s_box[li];
        const float bx1 = __fsub_rn(pb.x, __fmul_rn(0.5f, pb.z));
        const float by1 = __fsub_rn(pb.y, __fmul_rn(0.5f, pb.w));
        const float bx2 = __fadd_rn(pb.x, __fmul_rn(0.5f, pb.z));
        const float by2 = __fadd_rn(pb.y, __fmul_rn(0.5f, pb.w));
        const float ai  = __fmul_rn(__fsub_rn(bx2, bx1), __fsub_rn(by2, by1));
        const bool negi = (s_seed[li] == 0.0f);

        for (int j = t; j < NQ; j += 256) {
            const float4 q = s_box[j];
            const float qx1 = __fsub_rn(q.x, __fmul_rn(0.5f, q.z));
            const float qy1 = __fsub_rn(q.y, __fmul_rn(0.5f, q.w));
            const float qx2 = __fadd_rn(q.x, __fmul_rn(0.5f, q.z));
            const float qy2 = __fadd_rn(q.y, __fmul_rn(0.5f, q.w));
            const float aj  = __fmul_rn(__fsub_rn(qx2, qx1), __fsub_rn(qy2, qy1));
            const float w = fmaxf(__fsub_rn(fminf(bx2, qx2), fmaxf(bx1, qx1)), 0.0f);
            const float h = fmaxf(__fsub_rn(fminf(by2, qy2), fmaxf(by1, qy1)), 0.0f);
            const float inter = __fmul_rn(w, h);
            const float uni = __fsub_rn(__fadd_rn(ai, aj), inter);
            const float iou = __fdiv_rn(inter, uni);
            const bool attn = (iou >= 0.5f);
            out_mask[(size_t)row * NQ + j] = attn ? 1.0f : 0.0f;
            if (attn && negi && (s_seed[j] != 0.0f)) {
                int p = atomicAdd(&s_cnt, 1);
                if (p < 256) { sval[p] = iou; sidx[p] = j; }
            }
        }
        __syncthreads();

        if (t == 0) {
            int cnt = min(s_cnt, 256);
            int m;
            int sel[TOPK];
            if (cnt <= TOPK) {
                m = cnt;
                for (int qq = 0; qq < cnt; qq++) sel[qq] = sidx[qq];
            } else {
                m = TOPK;
                for (int rr = 0; rr < TOPK; rr++) {
                    float best = -1.0f; int bj = 0x7fffffff; int bp = -1;
                    for (int p = 0; p < cnt; p++) {
                        float v = sval[p]; int j = sidx[p];
                        if (v > best || (v == best && j < bj)) { best = v; bj = j; bp = p; }
                    }
                    sel[rr] = bj;
                    sval[bp] = -1.0f;
                }
            }
            s_m = m;
            if (m > 0) {
                int pbase = atomicAdd(&g_pair_count, m);
                for (int qq = 0; qq < m; qq++) {
                    g_pairs[2 * (pbase + qq)]     = row;
                    g_pairs[2 * (pbase + qq) + 1] = sel[qq];
                    g_flag[b * NQ + sel[qq]] = 1;
                }
                g_flag[row] = 1;
                int op = atomicAdd(&g_nout, 1);
                g_outrows[op] = row;
            }
        }
        __syncthreads();
        const int m = s_m;
        if (m == 0) {
            const float neg = 1.0f - s_seed[li];
            out[(size_t)row * D + t] = tgt[(size_t)row * D + t] + rb5 * neg;
        } else {
            g_cur[(size_t)row * D + t] = (m < TOPK) ? 0.0f : -CUDART_INF_F;
        }
    }
}

// ---------------- compaction of id-rows ----------------
__global__ void k_compact() {
    const int i = blockIdx.x * 256 + threadIdx.x;
    if (i < NROWS && g_flag[i]) {
        int p = atomicAdd(&g_nid, 1);
        g_idrows[p] = i;
    }
}

// ---------------- K3: P = (LN(relu(tgt@W1+b1)@W2+b2)*g2+be2) @ W3 ----------------
__global__ __launch_bounds__(256) void k_idtoken(
    const float* __restrict__ tgt,
    const float* __restrict__ W1, const float* __restrict__ b1,
    const float* __restrict__ W2, const float* __restrict__ b2,
    const float* __restrict__ g2, const float* __restrict__ be2,
    const float* __restrict__ W3)
{
    extern __shared__ float sm[];
    float* Xs = sm;                       // GROUP * XSTR
    float* Ws = sm + GROUP * XSTR;        // KC * XSTR
    __shared__ int   srow[GROUP];
    __shared__ float s_mean[GROUP], s_rstd[GROUP];

    const int t = threadIdx.x;
    const int w = t >> 5, lane = t & 31;
    const int h = w & 1, q = w >> 1;
    const int g = lane >> 2, tig = lane & 3;
    const int nact = g_nid;

    const float gv = g2[t], bev = be2[t];   // col = t for LN-transform pass

    for (int g0 = blockIdx.x * GROUP; g0 < nact; g0 += gridDim.x * GROUP) {
        if (t < GROUP) srow[t] = (g0 + t < nact) ? g_idrows[g0 + t] : -1;
        __syncthreads();

        // stage X = tgt rows (split pairs)
#pragma unroll
        for (int i = 0; i < 8; i++) {
            const int idx = t + (i << 8);           // float4 index over 32*64
            const int r = idx >> 6, c4 = (idx & 63) << 2;
            const int rr = srow[r];
            const float4 v = (rr >= 0) ? *(const float4*)(tgt + (size_t)rr * D + c4)
                                       : make_float4(0.f, 0.f, 0.f, 0.f);
            split4_store(Xs + r * XSTR + (c4 << 1), v);
        }

        float C[8][4];
        // layer 1
        mma_layer(Xs, Ws, W1, C, h, q, g, tig, t);
        __syncthreads();
#pragma unroll
        for (int nt = 0; nt < 8; nt++) {
            const int col = q * 64 + nt * 8 + (tig << 1);
            const float2 bb = *(const float2*)(b1 + col);
            const int r0 = h * 16 + g, r1 = r0 + 8;
            split2_store(Xs + r0 * XSTR + (col << 1),
                         fmaxf(C[nt][0] + bb.x, 0.f), fmaxf(C[nt][1] + bb.y, 0.f));
            split2_store(Xs + r1 * XSTR + (col << 1),
                         fmaxf(C[nt][2] + bb.x, 0.f), fmaxf(C[nt][3] + bb.y, 0.f));
        }

        // layer 2 (pre-LN z)
        mma_layer(Xs, Ws, W2, C, h, q, g, tig, t);
        __syncthreads();
#pragma unroll
        for (int nt = 0; nt < 8; nt++) {
            const int col = q * 64 + nt * 8 + (tig << 1);
            const float2 bb = *(const float2*)(b2 + col);
            const int r0 = h * 16 + g, r1 = r0 + 8;
            split2_store(Xs + r0 * XSTR + (col << 1), C[nt][0] + bb.x, C[nt][1] + bb.y);
            split2_store(Xs + r1 * XSTR + (col << 1), C[nt][2] + bb.x, C[nt][3] + bb.y);
        }
        __syncthreads();

        // LN stats: warp w handles rows 4w..4w+3 (z = hi + lo exactly)
        for (int rr = (w << 2); rr < (w << 2) + 4; rr++) {
            float s = 0.f, sq = 0.f;
            for (int c = lane; c < D; c += 32) {
                const float2 pz = *(const float2*)(Xs + rr * XSTR + (c << 1));
                const float z = pz.x + pz.y;
                s += z; sq += z * z;
            }
#pragma unroll
            for (int off = 16; off > 0; off >>= 1) {
                s  += __shfl_down_sync(0xffffffff, s,  off);
                sq += __shfl_down_sync(0xffffffff, sq, off);
            }
            if (lane == 0) {
                const float m = s * (1.0f / D);
                s_mean[rr] = m;
                s_rstd[rr] = rsqrtf(sq * (1.0f / D) - m * m + 1e-5f);
            }
        }
        __syncthreads();

        // LN transform: thread t = col t, loop rows
#pragma unroll 4
        for (int r = 0; r < GROUP; r++) {
            float* px = Xs + r * XSTR + (t << 1);
            const float z = px[0] + px[1];
            const float v = (z - s_mean[r]) * s_rstd[r] * gv + bev;
            float hi, lo; split_tf32(v, hi, lo);
            px[0] = hi; px[1] = lo;
        }

        // layer 3: P = id @ W3 (b3 applied at pair stage)
        mma_layer(Xs, Ws, W3, C, h, q, g, tig, t);
#pragma unroll
        for (int nt = 0; nt < 8; nt++) {
            const int col = q * 64 + nt * 8 + (tig << 1);
            const int r0 = h * 16 + g, r1 = r0 + 8;
            const int rw0 = srow[r0], rw1 = srow[r1];
            if (rw0 >= 0)
                *(float2*)(g_P + (size_t)rw0 * D + col) = make_float2(C[nt][0], C[nt][1]);
            if (rw1 >= 0)
                *(float2*)(g_P + (size_t)rw1 * D + col) = make_float2(C[nt][2], C[nt][3]);
        }
        __syncthreads();
    }
}

// ---------------- K4a: per-pair relu(P_i - P_j + b3) @ W4 + b4 -> seg-max + atomic ----------------
__global__ __launch_bounds__(256) void k_feat(
    const float* __restrict__ b3,
    const float* __restrict__ W4, const float* __restrict__ b4)
{
    extern __shared__ float sm[];
    float* Xs = sm;
    float* Ws = sm + GROUP * XSTR;     // doubles as Fs[32][260] after MMA
    __shared__ int spr[GROUP], sjj[GROUP];

    const int t = threadIdx.x;
    const int w = t >> 5, lane = t & 31;
    const int h = w & 1, q = w >> 1;
    const int g = lane >> 2, tig = lane & 3;
    const int npairs = g_pair_count;

    const float bias4 = b4[t];   // col = t for reduce phase

    for (int g0 = blockIdx.x * GROUP; g0 < npairs; g0 += gridDim.x * GROUP) {
        if (t < GROUP) {
            if (g0 + t < npairs) {
                spr[t] = g_pairs[2 * (g0 + t)];
                sjj[t] = g_pairs[2 * (g0 + t) + 1];
            } else spr[t] = -1;
        }
        __syncthreads();

        // stage X = relu(P_i - P_j + b3) (split pairs)
#pragma unroll
        for (int i = 0; i < 8; i++) {
            const int idx = t + (i << 8);
            const int p = idx >> 6, c4 = (idx & 63) << 2;
            const int rp = spr[p];
            float4 v = make_float4(0.f, 0.f, 0.f, 0.f);
            if (rp >= 0) {
                const int jab = (rp / NQ) * NQ + sjj[p];
                const float4 a  = *(const float4*)(g_P + (size_t)rp  * D + c4);
                const float4 nb = *(const float4*)(g_P + (size_t)jab * D + c4);
                const float4 bv = *(const float4*)(b3 + c4);
                v.x = fmaxf(a.x - nb.x + bv.x, 0.f);
                v.y = fmaxf(a.y - nb.y + bv.y, 0.f);
                v.z = fmaxf(a.z - nb.z + bv.z, 0.f);
                v.w = fmaxf(a.w - nb.w + bv.w, 0.f);
            }
            split4_store(Xs + p * XSTR + (c4 << 1), v);
        }

        float C[8][4];
        mma_layer(Xs, Ws, W4, C, h, q, g, tig, t);
        __syncthreads();

        // dump features to Fs = Ws (stride 260)
#pragma unroll
        for (int nt = 0; nt < 8; nt++) {
            const int col = q * 64 + nt * 8 + (tig << 1);
            const int p0 = h * 16 + g, p1 = p0 + 8;
            *(float2*)(Ws + p0 * 260 + col) = make_float2(C[nt][0], C[nt][1]);
            *(float2*)(Ws + p1 * 260 + col) = make_float2(C[nt][2], C[nt][3]);
        }
        __syncthreads();

        // segmented max over consecutive same-row pairs, then one atomic per run
        {
            int curRow = -1; float curMax = 0.f;
            for (int p = 0; p < GROUP; p++) {
                const int rp = spr[p];
                if (rp < 0) break;
                const float v = Ws[p * 260 + t] + bias4;
                if (rp != curRow) {
                    if (curRow >= 0) atomicMaxFloat(&g_cur[(size_t)curRow * D + t], curMax);
                    curRow = rp; curMax = v;
                } else {
                    curMax = fmaxf(curMax, v);
                }
            }
            if (curRow >= 0) atomicMaxFloat(&g_cur[(size_t)curRow * D + t], curMax);
        }
        __syncthreads();
    }
}

// ---------------- K4b: out = tgt + relu(cur@W5+b5) for active rows ----------------
__global__ __launch_bounds__(256) void k_out_gemv(
    const float* __restrict__ tgt,
    const float* __restrict__ W5, const float* __restrict__ b5,
    float* __restrict__ out)
{
    extern __shared__ float sm[];
    float* Xs = sm;
    float* Ws = sm + GROUP * XSTR;
    __shared__ int srow[GROUP];

    const int t = threadIdx.x;
    const int w = t >> 5, lane = t & 31;
    const int h = w & 1, q = w >> 1;
    const int g = lane >> 2, tig = lane & 3;
    const int nact = g_nout;

    for (int g0 = blockIdx.x * GROUP; g0 < nact; g0 += gridDim.x * GROUP) {
        if (t < GROUP) srow[t] = (g0 + t < nact) ? g_outrows[g0 + t] : -1;
        __syncthreads();

#pragma unroll
        for (int i = 0; i < 8; i++) {
            const int idx = t + (i << 8);
            const int r = idx >> 6, c4 = (idx & 63) << 2;
            const int rr = srow[r];
            const float4 v = (rr >= 0) ? *(const float4*)(g_cur + (size_t)rr * D + c4)
                                       : make_float4(0.f, 0.f, 0.f, 0.f);
            split4_store(Xs + r * XSTR + (c4 << 1), v);
        }

        float C[8][4];
        mma_layer(Xs, Ws, W5, C, h, q, g, tig, t);

#pragma unroll
        for (int nt = 0; nt < 8; nt++) {
            const int col = q * 64 + nt * 8 + (tig << 1);
            const float2 bb = *(const float2*)(b5 + col);
            const int r0 = h * 16 + g, r1 = r0 + 8;
            const int rw0 = srow[r0], rw1 = srow[r1];
            if (rw0 >= 0) {
                const float2 tg = *(const float2*)(tgt + (size_t)rw0 * D + col);
                *(float2*)(out + (size_t)rw0 * D + col) =
                    make_float2(tg.x + fmaxf(C[nt][0] + bb.x, 0.f),
                                tg.y + fmaxf(C[nt][1] + bb.y, 0.f));
            }
            if (rw1 >= 0) {
                const float2 tg = *(const float2*)(tgt + (size_t)rw1 * D + col);
                *(float2*)(out + (size_t)rw1 * D + col) =
                    make_float2(tg.x + fmaxf(C[nt][2] + bb.x, 0.f),
                                tg.y + fmaxf(C[nt][3] + bb.y, 0.f));
            }
        }
        __syncthreads();
    }
}

// ---------------- launch ----------------
extern "C" void kernel_launch(void* const* d_in, const int* in_sizes, int n_in,
                              void* d_out, int out_size) {
    const float* tgt  = (const float*)d_in[0];
    const float* seed = (const float*)d_in[1];
    const float* pred = (const float*)d_in[2];
    const float* W1 = (const float*)d_in[3];  const float* b1 = (const float*)d_in[4];
    const float* W2 = (const float*)d_in[5];  const float* b2 = (const float*)d_in[6];
    const float* g2 = (const float*)d_in[7];  const float* be2 = (const float*)d_in[8];
    const float* W3 = (const float*)d_in[9];  const float* b3 = (const float*)d_in[10];
    const float* W4 = (const float*)d_in[11]; const float* b4 = (const float*)d_in[12];
    const float* W5 = (const float*)d_in[13]; const float* b5 = (const float*)d_in[14];

    float* out = (float*)d_out;                 // cur_tgt: 8*1000*256 floats
    float* out_mask = out + (size_t)NROWS * D;  // attn_mask: 8*1000*1000 floats (0/1)

    static int smem_set = 0;
    if (!smem_set) {
        cudaFuncSetAttribute(k_idtoken, cudaFuncAttributeMaxDynamicSharedMemorySize, SMEM_MMA);
        cudaFuncSetAttribute(k_feat,    cudaFuncAttributeMaxDynamicSharedMemorySize, SMEM_MMA);
        cudaFuncSetAttribute(k_out_gemv,cudaFuncAttributeMaxDynamicSharedMemorySize, SMEM_MMA);
        smem_set = 1;
    }

    k_reset<<<(NROWS + 255) / 256, 256>>>();
    k_mask_sel<<<NROWS / MROWS, 256>>>(pred, seed, tgt, b5, out, out_mask);
    k_compact<<<(NROWS + 255) / 256, 256>>>();
    k_idtoken<<<GRID_MMA, 256, SMEM_MMA>>>(tgt, W1, b1, W2, b2, g2, be2, W3);
    k_feat<<<GRID_MMA, 256, SMEM_MMA>>>(b3, W4, b4);
    k_out_gemv<<<GRID_MMA, 256, SMEM_MMA>>>(tgt, W5, b5, out);
}